// round 5
// baseline (speedup 1.0000x reference)
#include <cuda_runtime.h>

// Problem constants (fixed shapes for this problem instance)
#define Dz 64
#define Hy 128
#define Wx 128
#define NPTS (Dz * Hy * Wx)          // 1,048,576
#define TBITS 20
#define TSIZE (1 << TBITS)           // 1,048,576 slots
#define TMASK (TSIZE - 1)
#define LISTCAP (1 << 19)            // max distinct lattice vertices
#define SENT LISTCAP                 // sentinel compact id: row stays all-zero
#define LSTRIDE 8                    // padded lattice row (floats)

#define GB_BLOCKS 296                // grid for lattice-domain kernels (single wave)
#define GB_THREADS 128

// Scratch (device globals; zero-initialized at load). Key 0 == empty (packed
// hash is never 0). d_cid[slot] holds compact_id+1 (0 == unpublished).
__device__ int      d_keys[TSIZE];
__device__ int      d_cid[TSIZE];
__device__ int      d_hash[LISTCAP];
__device__ int      d_slotof[LISTCAP];
__device__ float    d_latA[(LISTCAP + 1) * LSTRIDE];
__device__ float    d_latB[(LISTCAP + 1) * LSTRIDE];
__device__ int2     d_nbr[4 * LISTCAP];   // per-direction (plus, minus) neighbor ids
__device__ int      d_count;
__device__ unsigned d_bar;                // software grid barrier ticket counter

// Software grid barrier. Valid because GB_BLOCKS*GB_THREADS fits in one wave
// (296 blocks, 128 thr, low regs -> all co-resident). Counter is monotonic;
// invariant: it is a multiple of gridDim.x at every barrier boundary, so all
// arrivals of one barrier compute the same release target.
__device__ __forceinline__ void gridbar() {
    __syncthreads();
    __threadfence();
    if (threadIdx.x == 0) {
        unsigned nb  = gridDim.x;
        unsigned old = atomicAdd(&d_bar, 1u);
        unsigned target = (old / nb + 1u) * nb;
        while (atomicAdd(&d_bar, 0u) < target) { __nanosleep(40); }
    }
    __syncthreads();
    __threadfence();
}

__device__ __forceinline__ unsigned tab_start(int h) {
    return ((unsigned)h * 2654435761u) >> (32 - TBITS);
}

// Insert key, return compact id. Winners allocate an id and publish it;
// losers spin until the winner publishes.
__device__ __forceinline__ int tab_insert(int h) {
    unsigned idx = tab_start(h);
    for (;;) {
        int prev = atomicCAS(&d_keys[idx], 0, h);
        if (prev == 0) {
            int id = atomicAdd(&d_count, 1);
            d_hash[id]   = h;
            d_slotof[id] = (int)idx;
            atomicExch(&d_cid[idx], id + 1);
            return id;
        }
        if (prev == h) {
            int c;
            while ((c = atomicAdd(&d_cid[idx], 0)) == 0) { }
            return c - 1;
        }
        idx = (idx + 1) & TMASK;
    }
}

// Lookup key -> compact id, or SENT if absent.
__device__ __forceinline__ int find_id(int h) {
    unsigned idx = tab_start(h);
    for (;;) {
        int k = d_keys[idx];
        if (k == h) return d_cid[idx] - 1;
        if (k == 0) return SENT;
        idx = (idx + 1) & TMASK;
    }
}

// Permutohedral lattice geometry: 4 packed keys + 4 barycentric weights.
__device__ __forceinline__ void lattice(float f0, float f1, float f2,
                                        int* hh, float* bary) {
    const float s0 = 2.3094010767585034f;
    const float s1 = 1.3333333333333333f;
    const float s2 = 0.9428090415820634f;
    float c0 = f0 * s0, c1 = f1 * s1, c2 = f2 * s2;
    float el[4];
    el[0] =  c0 + c1 + c2;
    el[1] = -c0 + c1 + c2;
    el[2] = -2.f * c1 + c2;
    el[3] = -3.f * c2;

    float rem0[4];
    float sum = 0.f;
#pragma unroll
    for (int i = 0; i < 4; i++) {
        float r = rintf(el[i] * 0.25f) * 4.f;
        rem0[i] = r;
        sum += r;
    }

    float diff[4];
    int rank[4] = {0, 0, 0, 0};
#pragma unroll
    for (int i = 0; i < 4; i++) diff[i] = el[i] - rem0[i];
#pragma unroll
    for (int i = 0; i < 4; i++) {
#pragma unroll
        for (int j = i + 1; j < 4; j++) {
            if (diff[i] < diff[j]) rank[i]++; else rank[j]++;
        }
    }

    int off = (int)rintf(sum * 0.25f);
#pragma unroll
    for (int i = 0; i < 4; i++) {
        rank[i] += off;
        if (rank[i] < 0)      { rank[i] += 4; rem0[i] += 4.f; }
        else if (rank[i] > 3) { rank[i] -= 4; rem0[i] -= 4.f; }
    }

    float b[5] = {0.f, 0.f, 0.f, 0.f, 0.f};
#pragma unroll
    for (int i = 0; i < 4; i++) {
        float t = (el[i] - rem0[i]) * 0.25f;
        b[3 - rank[i]] += t;
        b[4 - rank[i]] -= t;
    }
    b[0] += 1.f + b[4];

    int r0 = (int)rem0[0], r1 = (int)rem0[1], r2 = (int)rem0[2];
#pragma unroll
    for (int r = 0; r < 4; r++) {
        int k0 = r0 + ((rank[0] >= 4 - r) ? r - 4 : r);
        int k1 = r1 + ((rank[1] >= 4 - r) ? r - 4 : r);
        int k2 = r2 + ((rank[2] >= 4 - r) ? r - 4 : r);
        hh[r]  = ((k0 + 512) << 20) + ((k1 + 512) << 10) + (k2 + 512);
        bary[r] = b[r];
    }
}

__device__ __forceinline__ void point_features(int n, const float* vg, const float* sg,
                                               float& f0, float& f1, float& f2) {
    int x = n & (Wx - 1);
    int y = (n >> 7) & (Hy - 1);
    int z = n >> 14;
    f0 = vg[0] * (float)z / sg[0];
    f1 = vg[2] * (float)y / sg[2];
    f2 = vg[1] * (float)x / sg[1];
}

__global__ void k_splat(const float* __restrict__ vals,
                        const float* __restrict__ vg,
                        const float* __restrict__ sg) {
    int n = blockIdx.x * blockDim.x + threadIdx.x;
    float f0, f1, f2;
    point_features(n, vg, sg, f0, f1, f2);

    int hh[4]; float bary[4];
    lattice(f0, f1, f2, hh, bary);

    float v0 = vals[n];
    float v1 = vals[NPTS + n];
    float v2 = vals[2 * NPTS + n];
    float v3 = vals[3 * NPTS + n];

    int lane = threadIdx.x & 31;

#pragma unroll
    for (int r = 0; r < 4; r++) {
        int   h = hh[r];
        float w = bary[r];
        float a0 = w * v0, a1 = w * v1, a2 = w * v2, a3 = w * v3, a4 = w;

        // Segmented warp reduction: equal keys form (mostly) contiguous runs.
        int  hprev = __shfl_up_sync(0xffffffffu, h, 1);
        bool head  = (lane == 0) || (hprev != h);
        unsigned heads = __ballot_sync(0xffffffffu, head);
        unsigned above = (lane == 31) ? 0u : (heads & ~((2u << lane) - 1u));
        int end = above ? (__ffs(above) - 2) : 31;   // last lane of my segment

#pragma unroll
        for (int d = 1; d < 32; d <<= 1) {
            float t0 = __shfl_down_sync(0xffffffffu, a0, d);
            float t1 = __shfl_down_sync(0xffffffffu, a1, d);
            float t2 = __shfl_down_sync(0xffffffffu, a2, d);
            float t3 = __shfl_down_sync(0xffffffffu, a3, d);
            float t4 = __shfl_down_sync(0xffffffffu, a4, d);
            if (lane + d <= end) { a0 += t0; a1 += t1; a2 += t2; a3 += t3; a4 += t4; }
        }

        if (head) {
            int id = tab_insert(h);
            float* p = &d_latA[(size_t)id * LSTRIDE];
            atomicAdd(p + 0, a0);
            atomicAdd(p + 1, a1);
            atomicAdd(p + 2, a2);
            atomicAdd(p + 3, a3);
            atomicAdd(p + 4, a4);
        }
    }
}

// All 4 blur passes in one kernel. Phase A: resolve neighbor ids (8 independent
// probe chains per vertex). Then 4 ping-pong gather passes with grid barriers.
__global__ void k_blurfused(int dh0, int dh1, int dh2, int dh3) {
    const int total  = d_count;
    const int stride = gridDim.x * blockDim.x;
    const int tid0   = blockIdx.x * blockDim.x + threadIdx.x;
    const int dhs[4] = {dh0, dh1, dh2, dh3};

    for (int i = tid0; i < total; i += stride) {
        int h = d_hash[i];
#pragma unroll
        for (int k = 0; k < 4; k++) {
            int p = find_id(h + dhs[k]);
            int q = find_id(h - dhs[k]);
            d_nbr[k * LISTCAP + i] = make_int2(p, q);
        }
    }
    gridbar();

#pragma unroll
    for (int pass = 0; pass < 4; pass++) {
        const float* src = (pass & 1) ? d_latB : d_latA;
        float*       dst = (pass & 1) ? d_latA : d_latB;
        for (int i = tid0; i < total; i += stride) {
            int2 pq = d_nbr[pass * LISTCAP + i];
            float4 cs = *(const float4*)&src[(size_t)i * LSTRIDE];
            float4 cp = *(const float4*)&src[(size_t)pq.x * LSTRIDE];
            float4 cq = *(const float4*)&src[(size_t)pq.y * LSTRIDE];
            float  es = src[(size_t)i * LSTRIDE + 4];
            float  ep = src[(size_t)pq.x * LSTRIDE + 4];
            float  eq = src[(size_t)pq.y * LSTRIDE + 4];

            float4 o;
            o.x = cs.x + 0.5f * (cp.x + cq.x);
            o.y = cs.y + 0.5f * (cp.y + cq.y);
            o.z = cs.z + 0.5f * (cp.z + cq.z);
            o.w = cs.w + 0.5f * (cp.w + cq.w);
            *(float4*)&dst[(size_t)i * LSTRIDE] = o;
            dst[(size_t)i * LSTRIDE + 4] = es + 0.5f * (ep + eq);
        }
        if (pass < 3) gridbar();
    }
    // Final result lands in d_latA (pass 3 writes A).
}

__global__ void k_slice(const float* __restrict__ vg,
                        const float* __restrict__ sg,
                        float* __restrict__ out) {
    int n = blockIdx.x * blockDim.x + threadIdx.x;
    float f0, f1, f2;
    point_features(n, vg, sg, f0, f1, f2);

    int hh[4]; float bary[4];
    lattice(f0, f1, f2, hh, bary);

    float acc0 = 0.f, acc1 = 0.f, acc2 = 0.f, acc3 = 0.f, acc4 = 0.f;
#pragma unroll
    for (int r = 0; r < 4; r++) {
        int id = find_id(hh[r]);   // always present (inserted by splat)
        float w = bary[r];
        const float4 c = *(const float4*)&d_latA[(size_t)id * LSTRIDE];
        float        e = d_latA[(size_t)id * LSTRIDE + 4];
        acc0 += w * c.x;
        acc1 += w * c.y;
        acc2 += w * c.z;
        acc3 += w * c.w;
        acc4 += w * e;
    }
    const float alpha = 1.f / 1.125f;  // 1/(1 + 2^-PD)
    float norm = alpha * acc4 + 2.220446049250313e-16f;
    float inv  = 1.f / norm;
    out[0 * NPTS + n] = alpha * acc0 * inv;
    out[1 * NPTS + n] = alpha * acc1 * inv;
    out[2 * NPTS + n] = alpha * acc2 * inv;
    out[3 * NPTS + n] = alpha * acc3 * inv;
}

// Restore invariants for the next call: clear table entries and compact latA
// rows, then (after a grid barrier) reset the vertex counter. latB never needs
// clearing: its occupied rows are fully rewritten by blur pass 0 next call.
__global__ void k_cleanup() {
    int total  = d_count;
    int stride = gridDim.x * blockDim.x;
    for (int i = blockIdx.x * blockDim.x + threadIdx.x; i < total; i += stride) {
        int s = d_slotof[i];
        d_keys[s] = 0;
        d_cid[s]  = 0;
        *(float4*)&d_latA[(size_t)i * LSTRIDE] = make_float4(0.f, 0.f, 0.f, 0.f);
        d_latA[(size_t)i * LSTRIDE + 4] = 0.f;
    }
    gridbar();
    if (blockIdx.x == 0 && threadIdx.x == 0) d_count = 0;
}

extern "C" void kernel_launch(void* const* d_in, const int* in_sizes, int n_in,
                              void* d_out, int out_size) {
    const float* input = nullptr;
    const float* vg = nullptr;
    const float* sg = nullptr;
    for (int i = 0; i < n_in; i++) {
        if (in_sizes[i] == 4 * NPTS) input = (const float*)d_in[i];
        else if (in_sizes[i] == 3) {
            if (!vg) vg = (const float*)d_in[i];
            else     sg = (const float*)d_in[i];
        }
    }
    float* out = (float*)d_out;

    const int DH0 = -3 * (1 << 20) + (1 << 10) + 1;      // o = (-3, 1, 1)
    const int DH1 =      (1 << 20) - 3 * (1 << 10) + 1;  // o = (1, -3, 1)
    const int DH2 =      (1 << 20) + (1 << 10) - 3;      // o = (1, 1, -3)
    const int DH3 =      (1 << 20) + (1 << 10) + 1;      // o = (1, 1, 1)

    k_splat<<<NPTS / 256, 256>>>(input, vg, sg);
    k_blurfused<<<GB_BLOCKS, GB_THREADS>>>(DH0, DH1, DH2, DH3);
    k_slice<<<NPTS / 256, 256>>>(vg, sg, out);
    k_cleanup<<<GB_BLOCKS, GB_THREADS>>>();
}